// round 2
// baseline (speedup 1.0000x reference)
#include <cuda_runtime.h>
#include <math.h>

// Problem constants
constexpr int kB = 64, kN = 1024, kF = 16, kD = 64, kK = 20;
constexpr int kM = kB * kN;              // 65536 rows
constexpr float kEps = 1e-5f, kSlope = 0.2f;

// ---------------- scratch (device globals: allocation-free) ----------------
__device__ float  g_h[(size_t)kM * kD];      // 16 MB: h = data @ lin_w^T
__device__ float  g_out1[(size_t)kM * kD];   // 16 MB: pre-BN1 GNN output
__device__ float  g_si[kM];
__device__ float  g_sj[kM];
__device__ float  g_rnorm[kN];
__device__ float  g_emi[kN];
__device__ float  g_emj[kN];
__device__ float  g_cos[(size_t)kN * kN];    // 4 MB cosine Gram
__device__ int    g_idx[kN * kK];            // top-k indices
__device__ double g_sum1[kD], g_ssq1[kD], g_sum2[kD], g_ssq2[kD];
__device__ float  g_a1[kD], g_b1[kD], g_a2[kD], g_b2[kD];

// ---------------- kernel 1: norms, emb-att dots, zero accumulators ----------
__global__ void k_prep(const float* __restrict__ emb,
                       const float* __restrict__ aei,
                       const float* __restrict__ aej) {
    if (blockIdx.x == 0 && threadIdx.x < kD) {
        g_sum1[threadIdx.x] = 0.0; g_ssq1[threadIdx.x] = 0.0;
        g_sum2[threadIdx.x] = 0.0; g_ssq2[threadIdx.x] = 0.0;
    }
    int w = (blockIdx.x * blockDim.x + threadIdx.x) >> 5;
    int lane = threadIdx.x & 31;
    if (w >= kN) return;
    float e0 = emb[w * kD + lane], e1 = emb[w * kD + lane + 32];
    float ss = e0 * e0 + e1 * e1;
    float ei = e0 * aei[lane] + e1 * aei[lane + 32];
    float ej = e0 * aej[lane] + e1 * aej[lane + 32];
#pragma unroll
    for (int o = 16; o; o >>= 1) {
        ss += __shfl_xor_sync(0xffffffffu, ss, o);
        ei += __shfl_xor_sync(0xffffffffu, ei, o);
        ej += __shfl_xor_sync(0xffffffffu, ej, o);
    }
    if (lane == 0) {
        g_rnorm[w] = 1.0f / sqrtf(ss);
        g_emi[w] = ei;
        g_emj[w] = ej;
    }
}

// ---------------- kernel 2: cosine Gram matrix (tiled 64x64 GEMM) -----------
__global__ void k_cos(const float* __restrict__ emb) {
    __shared__ float As[kD][65];   // [k][row], padded: conflict-free
    __shared__ float Bs[kD][65];
    int t = threadIdx.x;
    int bn = blockIdx.y * 64, bm = blockIdx.x * 64;
    for (int idx = t; idx < 64 * 64; idx += 256) {
        int r = idx >> 6, k = idx & 63;
        As[k][r] = emb[(size_t)(bn + r) * kD + k];
        Bs[k][r] = emb[(size_t)(bm + r) * kD + k];
    }
    __syncthreads();
    int tx = t & 15, ty = t >> 4;
    float acc[4][4] = {};
#pragma unroll 4
    for (int k = 0; k < 64; k++) {
        float a[4], b[4];
#pragma unroll
        for (int i = 0; i < 4; i++) { a[i] = As[k][ty * 4 + i]; b[i] = Bs[k][tx * 4 + i]; }
#pragma unroll
        for (int i = 0; i < 4; i++)
#pragma unroll
            for (int j = 0; j < 4; j++) acc[i][j] += a[i] * b[j];
    }
#pragma unroll
    for (int i = 0; i < 4; i++) {
        int r = bn + ty * 4 + i;
        float rn = g_rnorm[r];
#pragma unroll
        for (int j = 0; j < 4; j++) {
            int c = bm + tx * 4 + j;
            g_cos[(size_t)r * kN + c] = acc[i][j] * rn * g_rnorm[c];
        }
    }
}

// ---------------- kernel 3: h = data @ lin_w^T, plus s_i / s_j --------------
__global__ void k_h(const float* __restrict__ data, const float* __restrict__ lin_w,
                    const float* __restrict__ att_i, const float* __restrict__ att_j) {
    __shared__ float lw[kF][kD];   // transposed [f][d]
    for (int idx = threadIdx.x; idx < kF * kD; idx += blockDim.x) {
        int f = idx >> 6, d = idx & 63;
        lw[f][d] = lin_w[d * kF + f];
    }
    __syncthreads();
    int lane = threadIdx.x & 31;
    int gw = (blockIdx.x * blockDim.x + threadIdx.x) >> 5;
    int nw = (gridDim.x * blockDim.x) >> 5;
    float ai0 = att_i[lane], ai1 = att_i[lane + 32];
    float aj0 = att_j[lane], aj1 = att_j[lane + 32];
    for (int r = gw; r < kM; r += nw) {
        const float4* dp = reinterpret_cast<const float4*>(data + (size_t)r * kF);
        float4 q0 = dp[0], q1 = dp[1], q2 = dp[2], q3 = dp[3];
        float df[16] = {q0.x, q0.y, q0.z, q0.w, q1.x, q1.y, q1.z, q1.w,
                        q2.x, q2.y, q2.z, q2.w, q3.x, q3.y, q3.z, q3.w};
        float h0 = 0.f, h1 = 0.f;
#pragma unroll
        for (int f = 0; f < 16; f++) {
            h0 += df[f] * lw[f][lane];
            h1 += df[f] * lw[f][lane + 32];
        }
        g_h[(size_t)r * kD + lane] = h0;
        g_h[(size_t)r * kD + lane + 32] = h1;
        float si = h0 * ai0 + h1 * ai1;
        float sj = h0 * aj0 + h1 * aj1;
#pragma unroll
        for (int o = 16; o; o >>= 1) {
            si += __shfl_xor_sync(0xffffffffu, si, o);
            sj += __shfl_xor_sync(0xffffffffu, sj, o);
        }
        if (lane == 0) {
            int n = r & (kN - 1);
            g_si[r] = si + g_emi[n];
            g_sj[r] = sj + g_emj[n];
        }
    }
}

// ---------------- kernel 4: top-20 per row (iterative argmax) ---------------
// Tie-break: lowest index wins (matches jax.lax.top_k stable ordering).
__global__ void k_topk() {
    __shared__ float cv[kN];
    __shared__ float wv[8];
    __shared__ int   wi[8];
    int n = blockIdx.x, t = threadIdx.x;
    for (int m = t; m < kN; m += 256) cv[m] = g_cos[(size_t)n * kN + m];
    __syncthreads();
    int lane = t & 31, wid = t >> 5;
    for (int r = 0; r < kK; r++) {
        float best = -INFINITY; int bi = 0x7fffffff;
        for (int m = t; m < kN; m += 256) {
            float v = cv[m];
            if (v > best) { best = v; bi = m; }
        }
#pragma unroll
        for (int o = 16; o; o >>= 1) {
            float ov = __shfl_xor_sync(0xffffffffu, best, o);
            int   oi = __shfl_xor_sync(0xffffffffu, bi, o);
            if (ov > best || (ov == best && oi < bi)) { best = ov; bi = oi; }
        }
        if (lane == 0) { wv[wid] = best; wi[wid] = bi; }
        __syncthreads();
        if (t == 0) {
            float bb = wv[0]; int ii = wi[0];
            for (int w = 1; w < 8; w++)
                if (wv[w] > bb || (wv[w] == bb && wi[w] < ii)) { bb = wv[w]; ii = wi[w]; }
            g_idx[n * kK + r] = ii;
            cv[ii] = -INFINITY;
        }
        __syncthreads();
    }
}

// ---------------- kernel 5: alpha softmax + gather-aggregate + BN1 stats ----
__global__ void k_main(const float* __restrict__ gnn_bias) {
    __shared__ float sa[8][kK];
    __shared__ int   sid[8][kK];
    __shared__ float rs[8][kD];
    __shared__ float rq[8][kD];
    int t = threadIdx.x, lane = t & 31, wid = t >> 5;
    int b = blockIdx.x >> 4;
    int n0 = (blockIdx.x & 15) * 64;
    float bias0 = gnn_bias[lane], bias1 = gnn_bias[lane + 32];
    float ts0 = 0.f, tq0 = 0.f, ts1 = 0.f, tq1 = 0.f;
    const float* hb = g_h + (size_t)b * kN * kD;
    for (int i = 0; i < 8; i++) {
        int n = n0 + wid * 8 + i;
        float a = -INFINITY; int id = 0;
        if (lane < kK) {
            id = g_idx[n * kK + lane];
            a = g_si[b * kN + n] + g_sj[b * kN + id];
            a = a > 0.f ? a : kSlope * a;       // leaky_relu(0.2)
        }
        float mx = a;
#pragma unroll
        for (int o = 16; o; o >>= 1) mx = fmaxf(mx, __shfl_xor_sync(0xffffffffu, mx, o));
        float e = (lane < kK) ? expf(a - mx) : 0.f;
        float s = e;
#pragma unroll
        for (int o = 16; o; o >>= 1) s += __shfl_xor_sync(0xffffffffu, s, o);
        if (lane < kK) { sa[wid][lane] = e / s; sid[wid][lane] = id; }
        __syncwarp();
        float acc0 = 0.f, acc1 = 0.f;
#pragma unroll
        for (int k = 0; k < kK; k++) {
            float w = sa[wid][k];
            const float* hp = hb + (size_t)sid[wid][k] * kD;
            acc0 += w * hp[lane];
            acc1 += w * hp[lane + 32];
        }
        float o0 = acc0 + bias0, o1 = acc1 + bias1;
        size_t off = ((size_t)(b * kN + n)) * kD;
        g_out1[off + lane] = o0;
        g_out1[off + lane + 32] = o1;
        ts0 += o0; tq0 += o0 * o0;
        ts1 += o1; tq1 += o1 * o1;
        __syncwarp();  // protect sa/sid reuse next iteration
    }
    rs[wid][lane] = ts0; rs[wid][lane + 32] = ts1;
    rq[wid][lane] = tq0; rq[wid][lane + 32] = tq1;
    __syncthreads();
    if (t < kD) {
        float s = 0.f, q = 0.f;
        for (int w = 0; w < 8; w++) { s += rs[w][t]; q += rq[w][t]; }
        atomicAdd(&g_sum1[t], (double)s);
        atomicAdd(&g_ssq1[t], (double)q);
    }
}

// ---------------- kernel 6/8: finalize BN affine (a*x+b form) ---------------
__global__ void k_fin(int pass, const float* __restrict__ gamma,
                      const float* __restrict__ beta) {
    int d = threadIdx.x;
    if (d >= kD) return;
    double s = pass ? g_sum2[d] : g_sum1[d];
    double q = pass ? g_ssq2[d] : g_ssq1[d];
    double m = s / (double)kM;
    double var = q / (double)kM - m * m;
    float inv = (float)(1.0 / sqrt(var + (double)kEps));
    float aa = gamma[d] * inv;
    float bb = beta[d] - (float)m * aa;
    if (pass) { g_a2[d] = aa; g_b2[d] = bb; }
    else      { g_a1[d] = aa; g_b1[d] = bb; }
}

// ---------------- kernel 7: BN2 statistics over rep = relu(bn1(out))*emb ----
__global__ void k_stats2(const float* __restrict__ emb) {
    int t = threadIdx.x;
    int c = t & 63, rg = t >> 6;
    float a1 = g_a1[c], b1 = g_b1[c];
    float ts = 0.f, tq = 0.f;
    int r0 = blockIdx.x * 64;
    for (int i = 0; i < 16; i++) {
        int r = r0 + rg * 16 + i;
        float x = g_out1[(size_t)r * kD + c];
        float y = fmaxf(fmaf(a1, x, b1), 0.f);
        float rep = y * emb[(size_t)(r & (kN - 1)) * kD + c];
        ts += rep; tq += rep * rep;
    }
    __shared__ float rs[4][kD], rq[4][kD];
    rs[rg][c] = ts; rq[rg][c] = tq;
    __syncthreads();
    if (t < kD) {
        float s = 0.f, q = 0.f;
        for (int g = 0; g < 4; g++) { s += rs[g][t]; q += rq[g][t]; }
        atomicAdd(&g_sum2[t], (double)s);
        atomicAdd(&g_ssq2[t], (double)q);
    }
}

// ---------------- kernel 9: final projection --------------------------------
__global__ void k_final(const float* __restrict__ emb, const float* __restrict__ out_w,
                        const float* __restrict__ out_b, float* __restrict__ out) {
    int lane = threadIdx.x & 31;
    int gw = (blockIdx.x * blockDim.x + threadIdx.x) >> 5;
    int nw = (gridDim.x * blockDim.x) >> 5;
    float a10 = g_a1[lane], b10 = g_b1[lane], a20 = g_a2[lane], b20 = g_b2[lane];
    float a11 = g_a1[lane + 32], b11 = g_b1[lane + 32];
    float a21 = g_a2[lane + 32], b21 = g_b2[lane + 32];
    float w0 = out_w[lane], w1 = out_w[lane + 32];
    float ob = out_b[0];
    for (int r = gw; r < kM; r += nw) {
        int n = r & (kN - 1);
        float x0 = g_out1[(size_t)r * kD + lane];
        float x1 = g_out1[(size_t)r * kD + lane + 32];
        float y0 = fmaxf(fmaf(a10, x0, b10), 0.f) * emb[(size_t)n * kD + lane];
        float y1 = fmaxf(fmaf(a11, x1, b11), 0.f) * emb[(size_t)n * kD + lane + 32];
        float z0 = fmaxf(fmaf(a20, y0, b20), 0.f);
        float z1 = fmaxf(fmaf(a21, y1, b21), 0.f);
        float sred = z0 * w0 + z1 * w1;
#pragma unroll
        for (int o = 16; o; o >>= 1) sred += __shfl_xor_sync(0xffffffffu, sred, o);
        if (lane == 0) out[r] = sred + ob;
    }
}

// ---------------- launch ----------------------------------------------------
extern "C" void kernel_launch(void* const* d_in, const int* in_sizes, int n_in,
                              void* d_out, int out_size) {
    const float* data     = (const float*)d_in[0];
    // d_in[1] = org_edge_index (int64) — unused by the reference
    const float* emb      = (const float*)d_in[2];
    const float* lin_w    = (const float*)d_in[3];
    const float* att_i    = (const float*)d_in[4];
    const float* att_j    = (const float*)d_in[5];
    const float* aei      = (const float*)d_in[6];
    const float* aej      = (const float*)d_in[7];
    const float* gnn_bias = (const float*)d_in[8];
    const float* g1       = (const float*)d_in[9];
    const float* b1       = (const float*)d_in[10];
    const float* g2       = (const float*)d_in[11];
    const float* b2       = (const float*)d_in[12];
    const float* out_w    = (const float*)d_in[13];
    const float* out_b    = (const float*)d_in[14];
    float* out = (float*)d_out;

    k_prep<<<128, 256>>>(emb, aei, aej);
    k_cos<<<dim3(16, 16), 256>>>(emb);
    k_h<<<2048, 256>>>(data, lin_w, att_i, att_j);
    k_topk<<<1024, 256>>>();
    k_main<<<1024, 256>>>(gnn_bias);
    k_fin<<<1, 64>>>(0, g1, b1);
    k_stats2<<<1024, 256>>>(emb);
    k_fin<<<1, 64>>>(1, g2, b2);
    k_final<<<512, 256>>>(emb, out_w, out_b, out);
}